// round 14
// baseline (speedup 1.0000x reference)
#include <cuda_runtime.h>
#include <cuda_bf16.h>
#include <stdint.h>

#define KNS 100000
#define KNT 50000
#define KE  600000
#define KD  128
#define BN_EPS 1e-5f
#define NBLK_G 782     // ceil(KNT/64) row tiles
#define KNT_PAD (NBLK_G * 64)
#define GRID_G 296     // persistent gemm blocks (2/SM)
#define NBLK_B 98      // builder blocks (resident)

// ---------------- scratch (static device memory; no allocations) ----------------
__device__ float g_y1[KNT * KD];
__device__ __align__(16) __nv_bfloat16 g_Ah[KNT_PAD * KD];  // pre-swizzled hi plane
__device__ __align__(16) __nv_bfloat16 g_Al[KNT_PAD * KD];  // pre-swizzled lo plane
__device__ int   g_counts[KNT];
__device__ int   g_offsets[KNT + 1];
__device__ int   g_cursor[KNT];
__device__ int   g_srcs[KE];
__device__ float g_psum[NBLK_G * KD];
__device__ float g_psq[NBLK_G * KD];
__device__ __align__(128) float g_scale[2 * KD];
__device__ __align__(128) float g_shift[2 * KD];
__device__ int   g_bsum[128];
__device__ unsigned g_bar;
__device__ unsigned g_bar2;
__device__ __align__(16) __nv_bfloat16 g_Wh[2 * KD * KD];
__device__ __align__(16) __nv_bfloat16 g_Wl[2 * KD * KD];

// ---------------- device-wide barriers (co-resident grids only) -------------------
__device__ __forceinline__ void gridbar(unsigned target) {
  __syncthreads();
  if (threadIdx.x == 0) {
    __threadfence();
    atomicAdd(&g_bar, 1u);
    while (*((volatile unsigned*)&g_bar) < target) {}
  }
  __syncthreads();
}

__device__ __forceinline__ void megabar(unsigned target) {
  __syncthreads();
  if (threadIdx.x == 0) {
    __threadfence();
    atomicAdd(&g_bar2, 1u);
    while (*((volatile unsigned*)&g_bar2) < target) {}
  }
  __syncthreads();
}

// ---------------- precompute hi/lo bf16 split of weights; reset barriers ----------
__global__ void splitw_kernel(const float* __restrict__ W1,
                              const float* __restrict__ W2) {
  int i = blockIdx.x * 256 + threadIdx.x;  // 0..8191, 4 elems each
  if (i == 0) { g_bar = 0; g_bar2 = 0; }
  if (i >= 8192) return;
  const float* W = (i < 4096) ? W1 : W2;
  int local = (i < 4096) ? i : (i - 4096);
  float4 v = *reinterpret_cast<const float4*>(W + local * 4);
  float arr[4] = {v.x, v.y, v.z, v.w};
  int o = i * 4;
#pragma unroll
  for (int j = 0; j < 4; j++) {
    __nv_bfloat16 h = __float2bfloat16_rn(arr[j]);
    g_Wh[o + j] = h;
    g_Wl[o + j] = __float2bfloat16_rn(arr[j] - __bfloat162float(h));
  }
}

__device__ __forceinline__ int warp_incl_scan(int x, int lane) {
#pragma unroll
  for (int o = 1; o < 32; o <<= 1) {
    int y = __shfl_up_sync(0xffffffffu, x, o);
    if (lane >= o) x += y;
  }
  return x;
}

// ------- builder: zero + histogram + exclusive scan + scatter in ONE kernel -------
__global__ void build_kernel(const int* __restrict__ src, const int* __restrict__ dst) {
  __shared__ int ws[16];
  __shared__ int sbase;
  int t = threadIdx.x, b = blockIdx.x;
  int i = b * 512 + t;
  int lane = t & 31, w = t >> 5;

  if (i < KNT) g_counts[i] = 0;
  gridbar(NBLK_B);

  const int4* dst4 = reinterpret_cast<const int4*>(dst);
  for (int e = i; e < KE / 4; e += NBLK_B * 512) {
    int4 d = dst4[e];
    atomicAdd(&g_counts[d.x], 1);
    atomicAdd(&g_counts[d.y], 1);
    atomicAdd(&g_counts[d.z], 1);
    atomicAdd(&g_counts[d.w], 1);
  }
  gridbar(2 * NBLK_B);

  int v = (i < KNT) ? __ldcg(&g_counts[i]) : 0;
  int x = warp_incl_scan(v, lane);
  if (lane == 31) ws[w] = x;
  __syncthreads();
  if (t < 16) {
    int y = ws[t];
#pragma unroll
    for (int o = 1; o < 16; o <<= 1) {
      int z = __shfl_up_sync(0xffffu, y, o);
      if (t >= o) y += z;
    }
    ws[t] = y;
  }
  __syncthreads();
  int incl = x + (w > 0 ? ws[w - 1] : 0);
  int ex = incl - v;
  if (t == 511) g_bsum[b] = incl;
  gridbar(3 * NBLK_B);

  int contrib = (t < b) ? __ldcg(&g_bsum[t]) : 0;
#pragma unroll
  for (int o = 16; o; o >>= 1) contrib += __shfl_down_sync(0xffffffffu, contrib, o);
  if (lane == 0) ws[w] = contrib;
  __syncthreads();
  if (t == 0) {
    int s = 0;
#pragma unroll
    for (int j = 0; j < 16; j++) s += ws[j];
    sbase = s;
  }
  __syncthreads();
  int off = ex + sbase;
  if (i < KNT) {
    g_offsets[i] = off;
    g_cursor[i] = off;
  }
  if (b == 0 && t == 0) g_offsets[KNT] = KE;
  gridbar(4 * NBLK_B);

  const int4* src4 = reinterpret_cast<const int4*>(src);
  for (int e = i; e < KE / 4; e += NBLK_B * 512) {
    int4 s = src4[e];
    int4 d = dst4[e];
    g_srcs[atomicAdd(&g_cursor[d.x], 1)] = s.x;
    g_srcs[atomicAdd(&g_cursor[d.y], 1)] = s.y;
    g_srcs[atomicAdd(&g_cursor[d.z], 1)] = s.z;
    g_srcs[atomicAdd(&g_cursor[d.w], 1)] = s.w;
  }
}

__device__ __forceinline__ void split2(float x0, float x1, uint32_t& hi, uint32_t& lo) {
  __nv_bfloat162 H = __floats2bfloat162_rn(x0, x1);
  float l0 = x0 - __bfloat162float(H.x);
  float l1 = x1 - __bfloat162float(H.y);
  __nv_bfloat162 L = __floats2bfloat162_rn(l0, l1);
  hi = *reinterpret_cast<uint32_t*>(&H);
  lo = *reinterpret_cast<uint32_t*>(&L);
}

// ---- aggregation: one warp per target, 8-way MLP; pre-swizzled bf16 hi/lo out ----
__global__ __launch_bounds__(256, 4) void aggregate_kernel(const float* __restrict__ xs,
                                                           const float* __restrict__ xt,
                                                           const float* __restrict__ eps) {
  int gw = (blockIdx.x * blockDim.x + threadIdx.x) >> 5;
  int lane = threadIdx.x & 31;
  if (gw >= KNT) return;
  float sc = 1.0f + eps[0];
  const float4* xs4 = reinterpret_cast<const float4*>(xs);
  float4 a = reinterpret_cast<const float4*>(xt)[(size_t)gw * 32 + lane];
  a.x *= sc; a.y *= sc; a.z *= sc; a.w *= sc;
  float4 a1 = make_float4(0.f, 0.f, 0.f, 0.f);
  float4 a2 = make_float4(0.f, 0.f, 0.f, 0.f);
  float4 a3 = make_float4(0.f, 0.f, 0.f, 0.f);
  int beg = g_offsets[gw], end = g_offsets[gw + 1];
  int i = beg;
  for (; i + 7 < end; i += 8) {
    int s0 = g_srcs[i],     s1 = g_srcs[i + 1], s2 = g_srcs[i + 2], s3 = g_srcs[i + 3];
    int s4 = g_srcs[i + 4], s5 = g_srcs[i + 5], s6 = g_srcs[i + 6], s7 = g_srcs[i + 7];
    float4 v0 = xs4[(size_t)s0 * 32 + lane];
    float4 v1 = xs4[(size_t)s1 * 32 + lane];
    float4 v2 = xs4[(size_t)s2 * 32 + lane];
    float4 v3 = xs4[(size_t)s3 * 32 + lane];
    float4 v4 = xs4[(size_t)s4 * 32 + lane];
    float4 v5 = xs4[(size_t)s5 * 32 + lane];
    float4 v6 = xs4[(size_t)s6 * 32 + lane];
    float4 v7 = xs4[(size_t)s7 * 32 + lane];
    a.x += v0.x;  a.y += v0.y;  a.z += v0.z;  a.w += v0.w;
    a1.x += v1.x; a1.y += v1.y; a1.z += v1.z; a1.w += v1.w;
    a2.x += v2.x; a2.y += v2.y; a2.z += v2.z; a2.w += v2.w;
    a3.x += v3.x; a3.y += v3.y; a3.z += v3.z; a3.w += v3.w;
    a.x += v4.x;  a.y += v4.y;  a.z += v4.z;  a.w += v4.w;
    a1.x += v5.x; a1.y += v5.y; a1.z += v5.z; a1.w += v5.w;
    a2.x += v6.x; a2.y += v6.y; a2.z += v6.z; a2.w += v6.w;
    a3.x += v7.x; a3.y += v7.y; a3.z += v7.z; a3.w += v7.w;
  }
  for (; i + 3 < end; i += 4) {
    int s0 = g_srcs[i], s1 = g_srcs[i + 1], s2 = g_srcs[i + 2], s3 = g_srcs[i + 3];
    float4 v0 = xs4[(size_t)s0 * 32 + lane];
    float4 v1 = xs4[(size_t)s1 * 32 + lane];
    float4 v2 = xs4[(size_t)s2 * 32 + lane];
    float4 v3 = xs4[(size_t)s3 * 32 + lane];
    a.x += v0.x;  a.y += v0.y;  a.z += v0.z;  a.w += v0.w;
    a1.x += v1.x; a1.y += v1.y; a1.z += v1.z; a1.w += v1.w;
    a2.x += v2.x; a2.y += v2.y; a2.z += v2.z; a2.w += v2.w;
    a3.x += v3.x; a3.y += v3.y; a3.z += v3.z; a3.w += v3.w;
  }
  for (; i < end; i++) {
    float4 v0 = xs4[(size_t)g_srcs[i] * 32 + lane];
    a.x += v0.x; a.y += v0.y; a.z += v0.z; a.w += v0.w;
  }
  a.x += a1.x + a2.x + a3.x;
  a.y += a1.y + a2.y + a3.y;
  a.z += a1.z + a2.z + a3.z;
  a.w += a1.w + a2.w + a3.w;
  // split to bf16 hi/lo, write pre-swizzled (swizzle depends on gw&7 only)
  uint32_t h0, l0, h1, l1;
  split2(a.x, a.y, h0, l0);
  split2(a.z, a.w, h1, l1);
  int chunk = lane >> 1, sub = (lane & 1) << 3;
  size_t db = (size_t)gw * 256 + (uint32_t)(((chunk ^ (gw & 7)) << 4) + sub);
  *reinterpret_cast<uint2*>(reinterpret_cast<char*>(g_Ah) + db) = make_uint2(h0, h1);
  *reinterpret_cast<uint2*>(reinterpret_cast<char*>(g_Al) + db) = make_uint2(l0, l1);
}

// ------- persistent mega kernel: gemm1 + bn1 + gemm2 + bn2 + finalize -------------
__device__ __forceinline__ void mma_bf16(float* c, const uint32_t* a,
                                         uint32_t b0, uint32_t b1) {
  asm volatile(
      "mma.sync.aligned.m16n8k16.row.col.f32.bf16.bf16.f32 "
      "{%0,%1,%2,%3}, {%4,%5,%6,%7}, {%8,%9}, {%0,%1,%2,%3};\n"
      : "+f"(c[0]), "+f"(c[1]), "+f"(c[2]), "+f"(c[3])
      : "r"(a[0]), "r"(a[1]), "r"(a[2]), "r"(a[3]), "r"(b0), "r"(b1));
}

__device__ __forceinline__ void ldsm4(uint32_t* r, uint32_t addr) {
  asm volatile("ldmatrix.sync.aligned.m8n8.x4.shared.b16 {%0,%1,%2,%3}, [%4];"
               : "=r"(r[0]), "=r"(r[1]), "=r"(r[2]), "=r"(r[3]) : "r"(addr));
}

__device__ __forceinline__ void cpasync16(uint32_t saddr, const void* gptr) {
  asm volatile("cp.async.ca.shared.global [%0], [%1], 16;" :: "r"(saddr), "l"(gptr));
}

#define WSM_BYTES 32768
#define ASM_BYTES 16384

#define LOAD_FRAGS(st, kc)                                              \
  {                                                                     \
    uint32_t aoff = (uint32_t)((((kc) + achoff) ^ aswz) << 4);          \
    uint32_t boff = (uint32_t)((((kc) + bchoff) ^ bswz) << 4);          \
    ldsm4(ah[st][0], arowaddr[0] + aoff);                               \
    ldsm4(ah[st][1], arowaddr[1] + aoff);                               \
    ldsm4(al[st][0], arowaddr[0] + aoff + ASM_BYTES);                   \
    ldsm4(al[st][1], arowaddr[1] + aoff + ASM_BYTES);                   \
    ldsm4(bh[st][0], browaddr[0] + boff);                               \
    ldsm4(bh[st][1], browaddr[1] + boff);                               \
    ldsm4(bl[st][0], browaddr[0] + boff + WSM_BYTES);                   \
    ldsm4(bl[st][1], browaddr[1] + boff + WSM_BYTES);                   \
  }

#define MMA_PASSES(st)                                                          \
  {                                                                             \
    _Pragma("unroll") for (int p = 0; p < 2; p++)                               \
        _Pragma("unroll") for (int mt = 0; mt < 2; mt++) {                      \
      mma_bf16(acc[mt * 4 + p * 2], ah[st][mt], bh[st][p][0], bh[st][p][1]);    \
      mma_bf16(acc[mt * 4 + p * 2 + 1], ah[st][mt], bh[st][p][2], bh[st][p][3]);\
    }                                                                           \
    _Pragma("unroll") for (int p = 0; p < 2; p++)                               \
        _Pragma("unroll") for (int mt = 0; mt < 2; mt++) {                      \
      mma_bf16(acc[mt * 4 + p * 2], al[st][mt], bh[st][p][0], bh[st][p][1]);    \
      mma_bf16(acc[mt * 4 + p * 2 + 1], al[st][mt], bh[st][p][2], bh[st][p][3]);\
    }                                                                           \
    _Pragma("unroll") for (int p = 0; p < 2; p++)                               \
        _Pragma("unroll") for (int mt = 0; mt < 2; mt++) {                      \
      mma_bf16(acc[mt * 4 + p * 2], ah[st][mt], bl[st][p][0], bl[st][p][1]);    \
      mma_bf16(acc[mt * 4 + p * 2 + 1], ah[st][mt], bl[st][p][2], bl[st][p][3]);\
    }                                                                           \
  }

// epilogue shared by both layers
#define GEMM_EPILOGUE(row0_)                                                        \
  {                                                                                 \
    int r0 = (row0_) + rb + rq;                                                     \
    int r1 = r0 + 16;                                                               \
    bool ok0 = r0 < KNT, ok1 = (r0 + 8) < KNT, ok2 = r1 < KNT, ok3 = (r1 + 8) < KNT;\
    _Pragma("unroll") for (int nt = 0; nt < 4; nt++) {                              \
      int col = cb + nt * 8 + kq2;                                                  \
      float bc0 = biasS[col], bc1 = biasS[col + 1];                                 \
      float s0 = 0.f, s1 = 0.f, q0 = 0.f, q1 = 0.f;                                 \
      _Pragma("unroll") for (int mt = 0; mt < 2; mt++) {                            \
        int rA = (row0_) + rb + mt * 16 + rq;                                       \
        bool va = mt ? ok2 : ok0;                                                   \
        bool vb = mt ? ok3 : ok1;                                                   \
        float* ap = acc[mt * 4 + nt];                                               \
        float y00 = ap[0] + bc0, y01 = ap[1] + bc1;                                 \
        float y10 = ap[2] + bc0, y11 = ap[3] + bc1;                                 \
        if (va) *reinterpret_cast<float2*>(out + (size_t)rA * 128 + col) =          \
            make_float2(y00, y01);                                                  \
        if (vb) *reinterpret_cast<float2*>(out + (size_t)(rA + 8) * 128 + col) =    \
            make_float2(y10, y11);                                                  \
        s0 += (va ? y00 : 0.f) + (vb ? y10 : 0.f);                                  \
        s1 += (va ? y01 : 0.f) + (vb ? y11 : 0.f);                                  \
        q0 += (va ? y00 * y00 : 0.f) + (vb ? y10 * y10 : 0.f);                      \
        q1 += (va ? y01 * y01 : 0.f) + (vb ? y11 * y11 : 0.f);                      \
      }                                                                             \
      _Pragma("unroll") for (int o = 16; o >= 4; o >>= 1) {                         \
        s0 += __shfl_xor_sync(0xffffffffu, s0, o);                                  \
        s1 += __shfl_xor_sync(0xffffffffu, s1, o);                                  \
        q0 += __shfl_xor_sync(0xffffffffu, q0, o);                                  \
        q1 += __shfl_xor_sync(0xffffffffu, q1, o);                                  \
      }                                                                             \
      if (rq == 0) {                                                                \
        int wp = w >> 2;                                                            \
        ssum[wp * 128 + col] = s0;                                                  \
        ssum[wp * 128 + col + 1] = s1;                                              \
        ssq[wp * 128 + col] = q0;                                                   \
        ssq[wp * 128 + col + 1] = q1;                                               \
      }                                                                             \
    }                                                                               \
  }

template <int LAYER>
__device__ __forceinline__ void gemm_layer(char* sm, const float* __restrict__ bias,
                                           float* __restrict__ out) {
  char* WhS = sm;                         // [0,32K) W hi, [32K,64K) W lo
  char* AhS = sm + 2 * WSM_BYTES;         // [64K,80K) A hi, [80K,96K) A lo
  float* biasS = reinterpret_cast<float*>(sm + 2 * WSM_BYTES + 2 * ASM_BYTES);  // 128
  float* ssum = biasS + 128;              // 2*128
  float* ssq = ssum + 256;                // 2*128
  float* scS = ssq + 256;                 // 128 (layer 2)
  float* shS = scS + 128;                 // 128 (layer 2)

  const __nv_bfloat16* GWh = g_Wh + (LAYER - 1) * KD * KD;
  const __nv_bfloat16* GWl = g_Wl + (LAYER - 1) * KD * KD;

  int t = threadIdx.x;
  int w = t >> 5, lane = t & 31;
  uint32_t wbase = (uint32_t)__cvta_generic_to_shared(WhS);
  uint32_t abase = (uint32_t)__cvta_generic_to_shared(AhS);

  if (t < 128) {
    biasS[t] = bias[t];
    if (LAYER == 2) {
      scS[t] = __ldcg(&g_scale[t]);
      shS[t] = __ldcg(&g_shift[t]);
    }
  }

  // ---- stage W hi/lo ONCE via cp.async: row r, 16B chunk c -> chunk c^(r&7) ----
  for (int idx = t; idx < 2048; idx += 256) {
    int r = idx >> 4, c = idx & 15;
    uint32_t db = (uint32_t)(r * 256 + ((c ^ (r & 7)) << 4));
    cpasync16(wbase + db, GWh + idx * 8);
    cpasync16(wbase + WSM_BYTES + db, GWl + idx * 8);
  }
  asm volatile("cp.async.commit_group;");

  // thread-invariant geometry
  int rq = lane >> 2;          // 0..7 (epilogue)
  int kq2 = (lane & 3) << 1;   // 0,2,4,6 (epilogue)
  int rb = (w >> 2) * 32;      // 2 row groups of 32
  int cb = (w & 3) * 32;       // 4 col groups of 32
  int n_lane = (lane & 7) + ((lane >> 4) << 3);
  int bchoff = (lane >> 3) & 1;
  int bswz = n_lane & 7;
  uint32_t browaddr[2];
#pragma unroll
  for (int p = 0; p < 2; p++) browaddr[p] = wbase + (cb + p * 16 + n_lane) * 256;
  int a15 = lane & 15, achoff = lane >> 4, aswz = lane & 7;
  uint32_t arowaddr[2];
#pragma unroll
  for (int mt = 0; mt < 2; mt++) arowaddr[mt] = abase + (rb + mt * 16 + a15) * 256;

  if (LAYER == 1) {
    // --- pipelined: A tiles are pre-split pre-swizzled; staging = linear cp.async ---
    int tile0 = blockIdx.x;
    if (tile0 < NBLK_G) {
      const char* srcH = reinterpret_cast<const char*>(g_Ah) + (size_t)tile0 * 64 * 256;
      const char* srcL = reinterpret_cast<const char*>(g_Al) + (size_t)tile0 * 64 * 256;
      for (int idx = t; idx < 1024; idx += 256) {
        cpasync16(abase + idx * 16, srcH + idx * 16);
        cpasync16(abase + ASM_BYTES + idx * 16, srcL + idx * 16);
      }
      asm volatile("cp.async.commit_group;");
    }
    for (int tile = blockIdx.x; tile < NBLK_G; tile += GRID_G) {
      int row0 = tile * 64;
      asm volatile("cp.async.wait_group 0;");
      __syncthreads();

      float acc[8][4];
#pragma unroll
      for (int i = 0; i < 8; i++)
#pragma unroll
        for (int j = 0; j < 4; j++) acc[i][j] = 0.f;

      uint32_t ah[2][2][4], al[2][2][4], bh[2][2][4], bl[2][2][4];
      LOAD_FRAGS(0, 0);
#pragma unroll
      for (int ks = 0; ks < 8; ks++) {
        const int cur = ks & 1;
        const int nxt = cur ^ 1;
        if (ks < 7) LOAD_FRAGS(nxt, 2 * (ks + 1));
        MMA_PASSES(cur);
      }
      __syncthreads();  // all warps done reading A planes

      int ntile = tile + GRID_G;
      if (ntile < NBLK_G) {  // prefetch next A tile; flies during epilogue
        const char* srcH = reinterpret_cast<const char*>(g_Ah) + (size_t)ntile * 64 * 256;
        const char* srcL = reinterpret_cast<const char*>(g_Al) + (size_t)ntile * 64 * 256;
        for (int idx = t; idx < 1024; idx += 256) {
          cpasync16(abase + idx * 16, srcH + idx * 16);
          cpasync16(abase + ASM_BYTES + idx * 16, srcL + idx * 16);
        }
        asm volatile("cp.async.commit_group;");
      }

      GEMM_EPILOGUE(row0);
      __syncthreads();
      if (t < 128) {
        g_psum[tile * 128 + t] = ssum[t] + ssum[128 + t];
        g_psq[tile * 128 + t] = ssq[t] + ssq[128 + t];
      }
    }
  } else {
    // --- layer 2: fp32 y1 + BN1 + ReLU + split staged per tile (params in smem) ---
    for (int tile = blockIdx.x; tile < NBLK_G; tile += GRID_G) {
      int row0 = tile * 64;
      __syncthreads();  // planes free (prev compute done); scS/shS visible

      for (int idx = t; idx < 2048; idx += 256) {
        int r = idx >> 5, c4 = idx & 31;
        int grow = row0 + r;
        float4 v = make_float4(0.f, 0.f, 0.f, 0.f);
        if (grow < KNT) v = *reinterpret_cast<const float4*>(g_y1 + (size_t)grow * 128 + c4 * 4);
        int c = c4 * 4;
        v.x = fmaxf(fmaf(scS[c + 0], v.x, shS[c + 0]), 0.f);
        v.y = fmaxf(fmaf(scS[c + 1], v.y, shS[c + 1]), 0.f);
        v.z = fmaxf(fmaf(scS[c + 2], v.z, shS[c + 2]), 0.f);
        v.w = fmaxf(fmaf(scS[c + 3], v.w, shS[c + 3]), 0.f);
        uint32_t h0, l0, h1, l1;
        split2(v.x, v.y, h0, l0);
        split2(v.z, v.w, h1, l1);
        int chunk = c4 >> 1, sub = (c4 & 1) << 3;
        int db = r * 256 + ((chunk ^ (r & 7)) << 4) + sub;
        *reinterpret_cast<uint2*>(AhS + db) = make_uint2(h0, h1);
        *reinterpret_cast<uint2*>(AhS + ASM_BYTES + db) = make_uint2(l0, l1);
      }
      asm volatile("cp.async.wait_group 0;");  // W resident (no-op after tile 0)
      __syncthreads();

      float acc[8][4];
#pragma unroll
      for (int i = 0; i < 8; i++)
#pragma unroll
        for (int j = 0; j < 4; j++) acc[i][j] = 0.f;

      uint32_t ah[2][2][4], al[2][2][4], bh[2][2][4], bl[2][2][4];
      LOAD_FRAGS(0, 0);
#pragma unroll
      for (int ks = 0; ks < 8; ks++) {
        const int cur = ks & 1;
        const int nxt = cur ^ 1;
        if (ks < 7) LOAD_FRAGS(nxt, 2 * (ks + 1));
        MMA_PASSES(cur);
      }

      GEMM_EPILOGUE(row0);
      __syncthreads();
      if (t < 128) {
        g_psum[tile * 128 + t] = ssum[t] + ssum[128 + t];
        g_psq[tile * 128 + t] = ssq[t] + ssq[128 + t];
      }
    }
  }
}

// in-kernel BN params: block col (<128) reduces its column (deterministic tree)
__device__ __forceinline__ void redparams_inline(char* sm, int which,
                                                 const float* __restrict__ gamma,
                                                 const float* __restrict__ beta) {
  if (blockIdx.x >= 128) return;
  float* rs = reinterpret_cast<float*>(sm);          // 256
  float* rq = rs + 256;                              // 256
  int t = threadIdx.x;
  int col = blockIdx.x;
  float s = 0.f, q = 0.f;
  for (int b = t; b < NBLK_G; b += 256) {
    s += __ldcg(&g_psum[b * 128 + col]);
    q += __ldcg(&g_psq[b * 128 + col]);
  }
  rs[t] = s;
  rq[t] = q;
  __syncthreads();
#pragma unroll
  for (int o = 128; o; o >>= 1) {
    if (t < o) {
      rs[t] += rs[t + o];
      rq[t] += rq[t + o];
    }
    __syncthreads();
  }
  if (t == 0) {
    float inv = 1.0f / (float)KNT;
    float mu = rs[0] * inv;
    float var = rq[0] * inv - mu * mu;
    float r = rsqrtf(var + BN_EPS);
    float sc = gamma[col] * r;
    g_scale[which * 128 + col] = sc;
    g_shift[which * 128 + col] = beta[col] - mu * sc;
  }
}

__global__ __launch_bounds__(256, 2) void mega_kernel(const float* __restrict__ b1,
                                                      const float* __restrict__ g1,
                                                      const float* __restrict__ be1,
                                                      const float* __restrict__ b2,
                                                      const float* __restrict__ g2,
                                                      const float* __restrict__ be2,
                                                      float* __restrict__ out) {
  extern __shared__ char sm[];
  int t = threadIdx.x;

  gemm_layer<1>(sm, b1, g_y1);
  megabar(1 * GRID_G);
  redparams_inline(sm, 0, g1, be1);
  megabar(2 * GRID_G);
  gemm_layer<2>(sm, b2, out);
  megabar(3 * GRID_G);
  redparams_inline(sm, 1, g2, be2);
  megabar(4 * GRID_G);

  // finalize: BN2 + ReLU over output (params to smem first)
  float* scS = reinterpret_cast<float*>(sm);      // 128
  float* shS = scS + 128;                         // 128
  if (t < 128) {
    scS[t] = __ldcg(&g_scale[128 + t]);
    shS[t] = __ldcg(&g_shift[128 + t]);
  }
  __syncthreads();
  float4* out4 = reinterpret_cast<float4*>(out);
  for (int i = blockIdx.x * 256 + t; i < KNT * 32; i += GRID_G * 256) {
    int c = (i & 31) << 2;
    float4 v = out4[i];
    v.x = fmaxf(fmaf(scS[c + 0], v.x, shS[c + 0]), 0.f);
    v.y = fmaxf(fmaf(scS[c + 1], v.y, shS[c + 1]), 0.f);
    v.z = fmaxf(fmaf(scS[c + 2], v.z, shS[c + 2]), 0.f);
    v.w = fmaxf(fmaf(scS[c + 3], v.w, shS[c + 3]), 0.f);
    out4[i] = v;
  }
}

// ---------------- launch ----------------
extern "C" void kernel_launch(void* const* d_in, const int* in_sizes, int n_in,
                              void* d_out, int out_size) {
  const float* x_s = (const float*)d_in[0];
  const float* x_t = (const float*)d_in[1];
  const int* src = (const int*)d_in[2];  // int32 (JAX x64 disabled)
  const int* dst = (const int*)d_in[3];
  const float* eps = (const float*)d_in[4];
  const float* W1 = (const float*)d_in[5];
  const float* b1 = (const float*)d_in[6];
  const float* g1 = (const float*)d_in[7];
  const float* be1 = (const float*)d_in[8];
  const float* W2 = (const float*)d_in[9];
  const float* b2 = (const float*)d_in[10];
  const float* g2 = (const float*)d_in[11];
  const float* be2 = (const float*)d_in[12];
  float* out = (float*)d_out;

  const int SMEM = 2 * WSM_BYTES + 2 * ASM_BYTES + (128 + 512 + 256) * 4;  // 101888 B
  cudaFuncSetAttribute(mega_kernel, cudaFuncAttributeMaxDynamicSharedMemorySize, SMEM);

  splitw_kernel<<<32, 256>>>(W1, W2);                                // #1 (resets bars)
  build_kernel<<<NBLK_B, 512>>>(src, dst);                           // #2 zero+hist+scan+scatter
  aggregate_kernel<<<(KNT * 32 + 255) / 256, 256>>>(x_s, x_t, eps);  // #3
  mega_kernel<<<GRID_G, 256, SMEM>>>(b1, g1, be1, b2, g2, be2, out); // #4 (profiled slot)
}

// round 15
// speedup vs baseline: 1.0430x; 1.0430x over previous
#include <cuda_runtime.h>
#include <cuda_bf16.h>
#include <stdint.h>

#define KNS 100000
#define KNT 50000
#define KE  600000
#define KD  128
#define BN_EPS 1e-5f
#define NBLK_G 782     // ceil(KNT/64) row tiles
#define KNT_PAD (NBLK_G * 64)
#define GRID_G 296     // persistent gemm blocks (2/SM)
#define NBLK_B 98      // builder blocks (resident)

// ---------------- scratch (static device memory; no allocations) ----------------
__device__ float g_y1[KNT * KD];
__device__ __align__(16) __nv_bfloat16 g_Ah[KNT_PAD * KD];  // pre-swizzled hi plane
__device__ __align__(16) __nv_bfloat16 g_Al[KNT_PAD * KD];  // pre-swizzled lo plane
__device__ int   g_counts[KNT];
__device__ int   g_offsets[KNT + 1];
__device__ int   g_cursor[KNT];
__device__ int   g_srcs[KE];
__device__ float g_psum[NBLK_G * KD];
__device__ float g_psq[NBLK_G * KD];
__device__ __align__(128) float g_scale[2 * KD];
__device__ __align__(128) float g_shift[2 * KD];
__device__ int   g_bsum[128];
__device__ unsigned g_bar;
__device__ unsigned g_bar2;
__device__ __align__(16) __nv_bfloat16 g_Wh[2 * KD * KD];
__device__ __align__(16) __nv_bfloat16 g_Wl[2 * KD * KD];

// ---------------- device-wide barriers (co-resident grids only) -------------------
__device__ __forceinline__ void gridbar(unsigned target) {
  __syncthreads();
  if (threadIdx.x == 0) {
    __threadfence();
    atomicAdd(&g_bar, 1u);
    while (*((volatile unsigned*)&g_bar) < target) {}
  }
  __syncthreads();
}

__device__ __forceinline__ void megabar(unsigned target) {
  __syncthreads();
  if (threadIdx.x == 0) {
    __threadfence();
    atomicAdd(&g_bar2, 1u);
    while (*((volatile unsigned*)&g_bar2) < target) {}
  }
  __syncthreads();
}

// ---------------- precompute hi/lo bf16 split of weights; reset barriers ----------
__global__ void splitw_kernel(const float* __restrict__ W1,
                              const float* __restrict__ W2) {
  int i = blockIdx.x * 256 + threadIdx.x;  // 0..8191, 4 elems each
  if (i == 0) { g_bar = 0; g_bar2 = 0; }
  if (i >= 8192) return;
  const float* W = (i < 4096) ? W1 : W2;
  int local = (i < 4096) ? i : (i - 4096);
  float4 v = *reinterpret_cast<const float4*>(W + local * 4);
  float arr[4] = {v.x, v.y, v.z, v.w};
  int o = i * 4;
#pragma unroll
  for (int j = 0; j < 4; j++) {
    __nv_bfloat16 h = __float2bfloat16_rn(arr[j]);
    g_Wh[o + j] = h;
    g_Wl[o + j] = __float2bfloat16_rn(arr[j] - __bfloat162float(h));
  }
}

__device__ __forceinline__ int warp_incl_scan(int x, int lane) {
#pragma unroll
  for (int o = 1; o < 32; o <<= 1) {
    int y = __shfl_up_sync(0xffffffffu, x, o);
    if (lane >= o) x += y;
  }
  return x;
}

// ------- builder: zero + histogram + exclusive scan + scatter in ONE kernel -------
__global__ void build_kernel(const int* __restrict__ src, const int* __restrict__ dst) {
  __shared__ int ws[16];
  __shared__ int sbase;
  int t = threadIdx.x, b = blockIdx.x;
  int i = b * 512 + t;
  int lane = t & 31, w = t >> 5;

  if (i < KNT) g_counts[i] = 0;
  gridbar(NBLK_B);

  const int4* dst4 = reinterpret_cast<const int4*>(dst);
  for (int e = i; e < KE / 4; e += NBLK_B * 512) {
    int4 d = dst4[e];
    atomicAdd(&g_counts[d.x], 1);
    atomicAdd(&g_counts[d.y], 1);
    atomicAdd(&g_counts[d.z], 1);
    atomicAdd(&g_counts[d.w], 1);
  }
  gridbar(2 * NBLK_B);

  int v = (i < KNT) ? __ldcg(&g_counts[i]) : 0;
  int x = warp_incl_scan(v, lane);
  if (lane == 31) ws[w] = x;
  __syncthreads();
  if (t < 16) {
    int y = ws[t];
#pragma unroll
    for (int o = 1; o < 16; o <<= 1) {
      int z = __shfl_up_sync(0xffffu, y, o);
      if (t >= o) y += z;
    }
    ws[t] = y;
  }
  __syncthreads();
  int incl = x + (w > 0 ? ws[w - 1] : 0);
  int ex = incl - v;
  if (t == 511) g_bsum[b] = incl;
  gridbar(3 * NBLK_B);

  int contrib = (t < b) ? __ldcg(&g_bsum[t]) : 0;
#pragma unroll
  for (int o = 16; o; o >>= 1) contrib += __shfl_down_sync(0xffffffffu, contrib, o);
  if (lane == 0) ws[w] = contrib;
  __syncthreads();
  if (t == 0) {
    int s = 0;
#pragma unroll
    for (int j = 0; j < 16; j++) s += ws[j];
    sbase = s;
  }
  __syncthreads();
  int off = ex + sbase;
  if (i < KNT) {
    g_offsets[i] = off;
    g_cursor[i] = off;
  }
  if (b == 0 && t == 0) g_offsets[KNT] = KE;
  gridbar(4 * NBLK_B);

  const int4* src4 = reinterpret_cast<const int4*>(src);
  for (int e = i; e < KE / 4; e += NBLK_B * 512) {
    int4 s = src4[e];
    int4 d = dst4[e];
    g_srcs[atomicAdd(&g_cursor[d.x], 1)] = s.x;
    g_srcs[atomicAdd(&g_cursor[d.y], 1)] = s.y;
    g_srcs[atomicAdd(&g_cursor[d.z], 1)] = s.z;
    g_srcs[atomicAdd(&g_cursor[d.w], 1)] = s.w;
  }
}

__device__ __forceinline__ void split2(float x0, float x1, uint32_t& hi, uint32_t& lo) {
  __nv_bfloat162 H = __floats2bfloat162_rn(x0, x1);
  float l0 = x0 - __bfloat162float(H.x);
  float l1 = x1 - __bfloat162float(H.y);
  __nv_bfloat162 L = __floats2bfloat162_rn(l0, l1);
  hi = *reinterpret_cast<uint32_t*>(&H);
  lo = *reinterpret_cast<uint32_t*>(&L);
}

// ---- aggregation: one warp per target, occ 6, MLP 4; pre-swizzled hi/lo out ----
__global__ __launch_bounds__(256, 6) void aggregate_kernel(const float* __restrict__ xs,
                                                           const float* __restrict__ xt,
                                                           const float* __restrict__ eps) {
  int gw = (blockIdx.x * blockDim.x + threadIdx.x) >> 5;
  int lane = threadIdx.x & 31;
  if (gw >= KNT) return;
  float sc = 1.0f + eps[0];
  const float4* xs4 = reinterpret_cast<const float4*>(xs);
  float4 a = reinterpret_cast<const float4*>(xt)[(size_t)gw * 32 + lane];
  a.x *= sc; a.y *= sc; a.z *= sc; a.w *= sc;
  float4 a1 = make_float4(0.f, 0.f, 0.f, 0.f);
  float4 a2 = make_float4(0.f, 0.f, 0.f, 0.f);
  float4 a3 = make_float4(0.f, 0.f, 0.f, 0.f);
  int beg = g_offsets[gw], end = g_offsets[gw + 1];
  int i = beg;
  for (; i + 3 < end; i += 4) {
    int s0 = g_srcs[i], s1 = g_srcs[i + 1], s2 = g_srcs[i + 2], s3 = g_srcs[i + 3];
    float4 v0 = xs4[(size_t)s0 * 32 + lane];
    float4 v1 = xs4[(size_t)s1 * 32 + lane];
    float4 v2 = xs4[(size_t)s2 * 32 + lane];
    float4 v3 = xs4[(size_t)s3 * 32 + lane];
    a.x += v0.x;  a.y += v0.y;  a.z += v0.z;  a.w += v0.w;
    a1.x += v1.x; a1.y += v1.y; a1.z += v1.z; a1.w += v1.w;
    a2.x += v2.x; a2.y += v2.y; a2.z += v2.z; a2.w += v2.w;
    a3.x += v3.x; a3.y += v3.y; a3.z += v3.z; a3.w += v3.w;
  }
  for (; i < end; i++) {
    float4 v0 = xs4[(size_t)g_srcs[i] * 32 + lane];
    a.x += v0.x; a.y += v0.y; a.z += v0.z; a.w += v0.w;
  }
  a.x += a1.x + a2.x + a3.x;
  a.y += a1.y + a2.y + a3.y;
  a.z += a1.z + a2.z + a3.z;
  a.w += a1.w + a2.w + a3.w;
  // split to bf16 hi/lo, write pre-swizzled (swizzle depends on gw&7 only)
  uint32_t h0, l0, h1, l1;
  split2(a.x, a.y, h0, l0);
  split2(a.z, a.w, h1, l1);
  int chunk = lane >> 1, sub = (lane & 1) << 3;
  size_t db = (size_t)gw * 256 + (uint32_t)(((chunk ^ (gw & 7)) << 4) + sub);
  *reinterpret_cast<uint2*>(reinterpret_cast<char*>(g_Ah) + db) = make_uint2(h0, h1);
  *reinterpret_cast<uint2*>(reinterpret_cast<char*>(g_Al) + db) = make_uint2(l0, l1);
}

// ------- persistent mega kernel: gemm1 + bn1 + gemm2 + bn2 + finalize -------------
__device__ __forceinline__ void mma_bf16(float* c, const uint32_t* a,
                                         uint32_t b0, uint32_t b1) {
  asm volatile(
      "mma.sync.aligned.m16n8k16.row.col.f32.bf16.bf16.f32 "
      "{%0,%1,%2,%3}, {%4,%5,%6,%7}, {%8,%9}, {%0,%1,%2,%3};\n"
      : "+f"(c[0]), "+f"(c[1]), "+f"(c[2]), "+f"(c[3])
      : "r"(a[0]), "r"(a[1]), "r"(a[2]), "r"(a[3]), "r"(b0), "r"(b1));
}

__device__ __forceinline__ void ldsm4(uint32_t* r, uint32_t addr) {
  asm volatile("ldmatrix.sync.aligned.m8n8.x4.shared.b16 {%0,%1,%2,%3}, [%4];"
               : "=r"(r[0]), "=r"(r[1]), "=r"(r[2]), "=r"(r[3]) : "r"(addr));
}

__device__ __forceinline__ void cpasync16(uint32_t saddr, const void* gptr) {
  asm volatile("cp.async.ca.shared.global [%0], [%1], 16;" :: "r"(saddr), "l"(gptr));
}

#define WSM_BYTES 32768
#define ASM_BYTES 16384

#define LOAD_FRAGS(st, kc)                                              \
  {                                                                     \
    uint32_t aoff = (uint32_t)((((kc) + achoff) ^ aswz) << 4);          \
    uint32_t boff = (uint32_t)((((kc) + bchoff) ^ bswz) << 4);          \
    ldsm4(ah[st][0], arowaddr[0] + aoff);                               \
    ldsm4(ah[st][1], arowaddr[1] + aoff);                               \
    ldsm4(al[st][0], arowaddr[0] + aoff + ASM_BYTES);                   \
    ldsm4(al[st][1], arowaddr[1] + aoff + ASM_BYTES);                   \
    ldsm4(bh[st][0], browaddr[0] + boff);                               \
    ldsm4(bh[st][1], browaddr[1] + boff);                               \
    ldsm4(bl[st][0], browaddr[0] + boff + WSM_BYTES);                   \
    ldsm4(bl[st][1], browaddr[1] + boff + WSM_BYTES);                   \
  }

#define MMA_PASSES(st)                                                          \
  {                                                                             \
    _Pragma("unroll") for (int p = 0; p < 2; p++)                               \
        _Pragma("unroll") for (int mt = 0; mt < 2; mt++) {                      \
      mma_bf16(acc[mt * 4 + p * 2], ah[st][mt], bh[st][p][0], bh[st][p][1]);    \
      mma_bf16(acc[mt * 4 + p * 2 + 1], ah[st][mt], bh[st][p][2], bh[st][p][3]);\
    }                                                                           \
    _Pragma("unroll") for (int p = 0; p < 2; p++)                               \
        _Pragma("unroll") for (int mt = 0; mt < 2; mt++) {                      \
      mma_bf16(acc[mt * 4 + p * 2], al[st][mt], bh[st][p][0], bh[st][p][1]);    \
      mma_bf16(acc[mt * 4 + p * 2 + 1], al[st][mt], bh[st][p][2], bh[st][p][3]);\
    }                                                                           \
    _Pragma("unroll") for (int p = 0; p < 2; p++)                               \
        _Pragma("unroll") for (int mt = 0; mt < 2; mt++) {                      \
      mma_bf16(acc[mt * 4 + p * 2], ah[st][mt], bl[st][p][0], bl[st][p][1]);    \
      mma_bf16(acc[mt * 4 + p * 2 + 1], ah[st][mt], bl[st][p][2], bl[st][p][3]);\
    }                                                                           \
  }

// epilogue shared by both layers
#define GEMM_EPILOGUE(row0_)                                                        \
  {                                                                                 \
    int r0 = (row0_) + rb + rq;                                                     \
    int r1 = r0 + 16;                                                               \
    bool ok0 = r0 < KNT, ok1 = (r0 + 8) < KNT, ok2 = r1 < KNT, ok3 = (r1 + 8) < KNT;\
    _Pragma("unroll") for (int nt = 0; nt < 4; nt++) {                              \
      int col = cb + nt * 8 + kq2;                                                  \
      float bc0 = biasS[col], bc1 = biasS[col + 1];                                 \
      float s0 = 0.f, s1 = 0.f, q0 = 0.f, q1 = 0.f;                                 \
      _Pragma("unroll") for (int mt = 0; mt < 2; mt++) {                            \
        int rA = (row0_) + rb + mt * 16 + rq;                                       \
        bool va = mt ? ok2 : ok0;                                                   \
        bool vb = mt ? ok3 : ok1;                                                   \
        float* ap = acc[mt * 4 + nt];                                               \
        float y00 = ap[0] + bc0, y01 = ap[1] + bc1;                                 \
        float y10 = ap[2] + bc0, y11 = ap[3] + bc1;                                 \
        if (va) *reinterpret_cast<float2*>(out + (size_t)rA * 128 + col) =          \
            make_float2(y00, y01);                                                  \
        if (vb) *reinterpret_cast<float2*>(out + (size_t)(rA + 8) * 128 + col) =    \
            make_float2(y10, y11);                                                  \
        s0 += (va ? y00 : 0.f) + (vb ? y10 : 0.f);                                  \
        s1 += (va ? y01 : 0.f) + (vb ? y11 : 0.f);                                  \
        q0 += (va ? y00 * y00 : 0.f) + (vb ? y10 * y10 : 0.f);                      \
        q1 += (va ? y01 * y01 : 0.f) + (vb ? y11 * y11 : 0.f);                      \
      }                                                                             \
      _Pragma("unroll") for (int o = 16; o >= 4; o >>= 1) {                         \
        s0 += __shfl_xor_sync(0xffffffffu, s0, o);                                  \
        s1 += __shfl_xor_sync(0xffffffffu, s1, o);                                  \
        q0 += __shfl_xor_sync(0xffffffffu, q0, o);                                  \
        q1 += __shfl_xor_sync(0xffffffffu, q1, o);                                  \
      }                                                                             \
      if (rq == 0) {                                                                \
        int wp = w >> 2;                                                            \
        ssum[wp * 128 + col] = s0;                                                  \
        ssum[wp * 128 + col + 1] = s1;                                              \
        ssq[wp * 128 + col] = q0;                                                   \
        ssq[wp * 128 + col + 1] = q1;                                               \
      }                                                                             \
    }                                                                               \
  }

template <int LAYER>
__device__ __forceinline__ void gemm_layer(char* sm, const float* __restrict__ bias,
                                           float* __restrict__ out) {
  char* WhS = sm;                         // [0,32K) W hi, [32K,64K) W lo
  char* AhS = sm + 2 * WSM_BYTES;         // [64K,80K) A hi, [80K,96K) A lo
  float* biasS = reinterpret_cast<float*>(sm + 2 * WSM_BYTES + 2 * ASM_BYTES);  // 128
  float* ssum = biasS + 128;              // 2*128
  float* ssq = ssum + 256;                // 2*128
  float* scS = ssq + 256;                 // 128 (layer 2)
  float* shS = scS + 128;                 // 128 (layer 2)

  const __nv_bfloat16* GWh = g_Wh + (LAYER - 1) * KD * KD;
  const __nv_bfloat16* GWl = g_Wl + (LAYER - 1) * KD * KD;

  int t = threadIdx.x;
  int w = t >> 5, lane = t & 31;
  uint32_t wbase = (uint32_t)__cvta_generic_to_shared(WhS);
  uint32_t abase = (uint32_t)__cvta_generic_to_shared(AhS);

  if (t < 128) {
    biasS[t] = bias[t];
    if (LAYER == 2) {
      scS[t] = __ldcg(&g_scale[t]);
      shS[t] = __ldcg(&g_shift[t]);
    }
  }

  // ---- stage W hi/lo ONCE via cp.async: row r, 16B chunk c -> chunk c^(r&7) ----
  for (int idx = t; idx < 2048; idx += 256) {
    int r = idx >> 4, c = idx & 15;
    uint32_t db = (uint32_t)(r * 256 + ((c ^ (r & 7)) << 4));
    cpasync16(wbase + db, GWh + idx * 8);
    cpasync16(wbase + WSM_BYTES + db, GWl + idx * 8);
  }
  asm volatile("cp.async.commit_group;");

  // thread-invariant geometry
  int rq = lane >> 2;          // 0..7 (epilogue)
  int kq2 = (lane & 3) << 1;   // 0,2,4,6 (epilogue)
  int rb = (w >> 2) * 32;      // 2 row groups of 32
  int cb = (w & 3) * 32;       // 4 col groups of 32
  int n_lane = (lane & 7) + ((lane >> 4) << 3);
  int bchoff = (lane >> 3) & 1;
  int bswz = n_lane & 7;
  uint32_t browaddr[2];
#pragma unroll
  for (int p = 0; p < 2; p++) browaddr[p] = wbase + (cb + p * 16 + n_lane) * 256;
  int a15 = lane & 15, achoff = lane >> 4, aswz = lane & 7;
  uint32_t arowaddr[2];
#pragma unroll
  for (int mt = 0; mt < 2; mt++) arowaddr[mt] = abase + (rb + mt * 16 + a15) * 256;

  if (LAYER == 1) {
    // --- pipelined: A tiles are pre-split pre-swizzled; staging = linear cp.async ---
    int tile0 = blockIdx.x;
    if (tile0 < NBLK_G) {
      const char* srcH = reinterpret_cast<const char*>(g_Ah) + (size_t)tile0 * 64 * 256;
      const char* srcL = reinterpret_cast<const char*>(g_Al) + (size_t)tile0 * 64 * 256;
      for (int idx = t; idx < 1024; idx += 256) {
        cpasync16(abase + idx * 16, srcH + idx * 16);
        cpasync16(abase + ASM_BYTES + idx * 16, srcL + idx * 16);
      }
      asm volatile("cp.async.commit_group;");
    }
    for (int tile = blockIdx.x; tile < NBLK_G; tile += GRID_G) {
      int row0 = tile * 64;
      asm volatile("cp.async.wait_group 0;");
      __syncthreads();

      float acc[8][4];
#pragma unroll
      for (int i = 0; i < 8; i++)
#pragma unroll
        for (int j = 0; j < 4; j++) acc[i][j] = 0.f;

      uint32_t ah[2][2][4], al[2][2][4], bh[2][2][4], bl[2][2][4];
      LOAD_FRAGS(0, 0);
#pragma unroll
      for (int ks = 0; ks < 8; ks++) {
        const int cur = ks & 1;
        const int nxt = cur ^ 1;
        if (ks < 7) LOAD_FRAGS(nxt, 2 * (ks + 1));
        MMA_PASSES(cur);
      }
      __syncthreads();  // all warps done reading A planes

      int ntile = tile + GRID_G;
      if (ntile < NBLK_G) {  // prefetch next A tile; flies during epilogue
        const char* srcH = reinterpret_cast<const char*>(g_Ah) + (size_t)ntile * 64 * 256;
        const char* srcL = reinterpret_cast<const char*>(g_Al) + (size_t)ntile * 64 * 256;
        for (int idx = t; idx < 1024; idx += 256) {
          cpasync16(abase + idx * 16, srcH + idx * 16);
          cpasync16(abase + ASM_BYTES + idx * 16, srcL + idx * 16);
        }
        asm volatile("cp.async.commit_group;");
      }

      GEMM_EPILOGUE(row0);
      __syncthreads();
      if (t < 128) {
        g_psum[tile * 128 + t] = ssum[t] + ssum[128 + t];
        g_psq[tile * 128 + t] = ssq[t] + ssq[128 + t];
      }
    }
  } else {
    // --- layer 2: fp32 y1 + BN1 + ReLU + split staged per tile (params in smem) ---
    for (int tile = blockIdx.x; tile < NBLK_G; tile += GRID_G) {
      int row0 = tile * 64;
      __syncthreads();  // planes free (prev compute done); scS/shS visible

      for (int idx = t; idx < 2048; idx += 256) {
        int r = idx >> 5, c4 = idx & 31;
        int grow = row0 + r;
        float4 v = make_float4(0.f, 0.f, 0.f, 0.f);
        if (grow < KNT) v = *reinterpret_cast<const float4*>(g_y1 + (size_t)grow * 128 + c4 * 4);
        int c = c4 * 4;
        v.x = fmaxf(fmaf(scS[c + 0], v.x, shS[c + 0]), 0.f);
        v.y = fmaxf(fmaf(scS[c + 1], v.y, shS[c + 1]), 0.f);
        v.z = fmaxf(fmaf(scS[c + 2], v.z, shS[c + 2]), 0.f);
        v.w = fmaxf(fmaf(scS[c + 3], v.w, shS[c + 3]), 0.f);
        uint32_t h0, l0, h1, l1;
        split2(v.x, v.y, h0, l0);
        split2(v.z, v.w, h1, l1);
        int chunk = c4 >> 1, sub = (c4 & 1) << 3;
        int db = r * 256 + ((chunk ^ (r & 7)) << 4) + sub;
        *reinterpret_cast<uint2*>(AhS + db) = make_uint2(h0, h1);
        *reinterpret_cast<uint2*>(AhS + ASM_BYTES + db) = make_uint2(l0, l1);
      }
      asm volatile("cp.async.wait_group 0;");  // W resident (no-op after tile 0)
      __syncthreads();

      float acc[8][4];
#pragma unroll
      for (int i = 0; i < 8; i++)
#pragma unroll
        for (int j = 0; j < 4; j++) acc[i][j] = 0.f;

      uint32_t ah[2][2][4], al[2][2][4], bh[2][2][4], bl[2][2][4];
      LOAD_FRAGS(0, 0);
#pragma unroll
      for (int ks = 0; ks < 8; ks++) {
        const int cur = ks & 1;
        const int nxt = cur ^ 1;
        if (ks < 7) LOAD_FRAGS(nxt, 2 * (ks + 1));
        MMA_PASSES(cur);
      }

      GEMM_EPILOGUE(row0);
      __syncthreads();
      if (t < 128) {
        g_psum[tile * 128 + t] = ssum[t] + ssum[128 + t];
        g_psq[tile * 128 + t] = ssq[t] + ssq[128 + t];
      }
    }
  }
}

// in-kernel BN params: block col (<128) reduces its column (deterministic tree)
__device__ __forceinline__ void redparams_inline(char* sm, int which,
                                                 const float* __restrict__ gamma,
                                                 const float* __restrict__ beta) {
  if (blockIdx.x >= 128) return;
  float* rs = reinterpret_cast<float*>(sm);          // 256
  float* rq = rs + 256;                              // 256
  int t = threadIdx.x;
  int col = blockIdx.x;
  float s = 0.f, q = 0.f;
  for (int b = t; b < NBLK_G; b += 256) {
    s += __ldcg(&g_psum[b * 128 + col]);
    q += __ldcg(&g_psq[b * 128 + col]);
  }
  rs[t] = s;
  rq[t] = q;
  __syncthreads();
#pragma unroll
  for (int o = 128; o; o >>= 1) {
    if (t < o) {
      rs[t] += rs[t + o];
      rq[t] += rq[t + o];
    }
    __syncthreads();
  }
  if (t == 0) {
    float inv = 1.0f / (float)KNT;
    float mu = rs[0] * inv;
    float var = rq[0] * inv - mu * mu;
    float r = rsqrtf(var + BN_EPS);
    float sc = gamma[col] * r;
    g_scale[which * 128 + col] = sc;
    g_shift[which * 128 + col] = beta[col] - mu * sc;
  }
}

__global__ __launch_bounds__(256, 2) void mega_kernel(const float* __restrict__ b1,
                                                      const float* __restrict__ g1,
                                                      const float* __restrict__ be1,
                                                      const float* __restrict__ b2,
                                                      const float* __restrict__ g2,
                                                      const float* __restrict__ be2,
                                                      float* __restrict__ out) {
  extern __shared__ char sm[];
  int t = threadIdx.x;

  gemm_layer<1>(sm, b1, g_y1);
  megabar(1 * GRID_G);
  redparams_inline(sm, 0, g1, be1);
  megabar(2 * GRID_G);
  gemm_layer<2>(sm, b2, out);
  megabar(3 * GRID_G);
  redparams_inline(sm, 1, g2, be2);
  megabar(4 * GRID_G);

  // finalize: BN2 + ReLU over output (params to smem first)
  float* scS = reinterpret_cast<float*>(sm);      // 128
  float* shS = scS + 128;                         // 128
  if (t < 128) {
    scS[t] = __ldcg(&g_scale[128 + t]);
    shS[t] = __ldcg(&g_shift[128 + t]);
  }
  __syncthreads();
  float4* out4 = reinterpret_cast<float4*>(out);
  for (int i = blockIdx.x * 256 + t; i < KNT * 32; i += GRID_G * 256) {
    int c = (i & 31) << 2;
    float4 v = out4[i];
    v.x = fmaxf(fmaf(scS[c + 0], v.x, shS[c + 0]), 0.f);
    v.y = fmaxf(fmaf(scS[c + 1], v.y, shS[c + 1]), 0.f);
    v.z = fmaxf(fmaf(scS[c + 2], v.z, shS[c + 2]), 0.f);
    v.w = fmaxf(fmaf(scS[c + 3], v.w, shS[c + 3]), 0.f);
    out4[i] = v;
  }
}

// ---------------- launch ----------------
extern "C" void kernel_launch(void* const* d_in, const int* in_sizes, int n_in,
                              void* d_out, int out_size) {
  const float* x_s = (const float*)d_in[0];
  const float* x_t = (const float*)d_in[1];
  const int* src = (const int*)d_in[2];  // int32 (JAX x64 disabled)
  const int* dst = (const int*)d_in[3];
  const float* eps = (const float*)d_in[4];
  const float* W1 = (const float*)d_in[5];
  const float* b1 = (const float*)d_in[6];
  const float* g1 = (const float*)d_in[7];
  const float* be1 = (const float*)d_in[8];
  const float* W2 = (const float*)d_in[9];
  const float* b2 = (const float*)d_in[10];
  const float* g2 = (const float*)d_in[11];
  const float* be2 = (const float*)d_in[12];
  float* out = (float*)d_out;

  const int SMEM = 2 * WSM_BYTES + 2 * ASM_BYTES + (128 + 512 + 256) * 4;  // 101888 B
  cudaFuncSetAttribute(mega_kernel, cudaFuncAttributeMaxDynamicSharedMemorySize, SMEM);

  splitw_kernel<<<32, 256>>>(W1, W2);                                // #1 (resets bars)
  build_kernel<<<NBLK_B, 512>>>(src, dst);                           // #2 zero+hist+scan+scatter
  aggregate_kernel<<<(KNT * 32 + 255) / 256, 256>>>(x_s, x_t, eps);  // #3
  mega_kernel<<<GRID_G, 256, SMEM>>>(b1, g1, be1, b2, g2, be2, out); // #4 (profiled slot)
}